// round 9
// baseline (speedup 1.0000x reference)
#include <cuda_runtime.h>
#include <math.h>

#define Bz   4
#define LQ   1024
#define Cc   256
#define Hh   8
#define Ll   4
#define Pp   4
#define DFF  1024
#define DH   32
#define LSRC 21760   // 128*128 + 64*64 + 32*32 + 16*16

// ---------------- scratch (static device globals; no allocation) ------------
__device__ float g_qk   [Bz*LQ*Cc];
__device__ float g_qkv  [Bz*LQ*768];
__device__ float g_att  [Bz*LQ*Cc];
__device__ float g_sa   [Bz*LQ*Cc];
__device__ float g_tgt1 [Bz*LQ*Cc];
__device__ float g_query[Bz*LQ*Cc];
__device__ float g_value[Bz*LSRC*Cc];
__device__ float g_offaw[Bz*LQ*384];
__device__ float g_samp [Bz*LQ*Cc];
__device__ float g_co   [Bz*LQ*Cc];
__device__ float g_tgt2 [Bz*LQ*Cc];
__device__ float g_ffn  [Bz*LQ*DFF];
__device__ float g_f2   [Bz*LQ*Cc];

// ---------------- elementwise add -------------------------------------------
__global__ void add2_kernel(const float4* __restrict__ a, const float4* __restrict__ b,
                            float4* __restrict__ o, int n4) {
    int i = blockIdx.x * blockDim.x + threadIdx.x;
    if (i < n4) {
        float4 x = a[i], y = b[i];
        x.x += y.x; x.y += y.y; x.z += y.z; x.w += y.w;
        o[i] = x;
    }
}

// ---------------- TF32 tensor-core GEMM with cp.async 3-stage pipeline ------
// C[M,N(out ldc)] = Asel[M,K] @ Wsel[N,K]^T + bias
// Block tile: BM x 128 (BM = MT*32), 256 threads, 8 warps (2 M x 4 N),
// warp tile (MT*16) x 32, mma.m16n8k8.tf32 (raw f32 operands, HW-truncated).
// A/W selected per n-block for fused launches (nsplitA / nsplitW).
// smem layout: [row][k] rows 0..BM-1 = A(m), BM..BM+127 = W(n); row stride 20.
#define SROW 20

__device__ __forceinline__ unsigned smem_u32(const void* p) {
    return (unsigned)__cvta_generic_to_shared(p);
}

template<int RELU, int MT>
__global__ __launch_bounds__(256)
void gemm_tc(const float* __restrict__ A, const float* __restrict__ A2, int nsplitA,
             const float* __restrict__ W, const float* __restrict__ W2, int nsplitW,
             const float* __restrict__ bias, const float* __restrict__ bias2,
             float* __restrict__ Cout, int ldc, int M, int N, int K) {
    constexpr int BM   = MT * 32;
    constexpr int BN   = 128;
    constexpr int NT   = 4;
    constexpr int ROWS = BM + BN;
    constexpr int SSZ  = ROWS * SROW;          // floats per stage
    constexpr int NCH  = ROWS * 4 / 256;       // 16B chunks per thread

    extern __shared__ float sm[];

    const int n0 = blockIdx.x * BN;
    const int m0 = blockIdx.y * BM;
    const int t  = threadIdx.x;
    const int lane = t & 31;
    const int wid  = t >> 5;
    const int wm   = (wid & 1) * MT * 16;
    const int wn   = (wid >> 1) * NT * 8;
    const int grp  = lane >> 2;
    const int tg   = lane & 3;

    const float* Ause = (n0 < nsplitA) ? A : A2;
    const float* Wuse;
    const float* buse;
    int nW;
    if (n0 < nsplitW) { Wuse = W;  buse = bias  + n0;            nW = n0; }
    else              { Wuse = W2; buse = bias2 + (n0 - nsplitW); nW = n0 - nsplitW; }

    // per-thread cp.async chunk sources / smem destinations
    const float* src[NCH];
    unsigned dst[NCH];
    #pragma unroll
    for (int i = 0; i < NCH; i++) {
        int chunk = t + i * 256;
        int row = chunk >> 2;
        int off = (chunk & 3) * 4;
        if (row < BM) src[i] = Ause + (size_t)(m0 + row) * K + off;
        else          src[i] = Wuse + (size_t)(nW + row - BM) * K + off;
        dst[i] = (unsigned)((row * SROW + off) * 4);
    }
    const unsigned sbase = smem_u32(sm);
    const int T = K / 16;

    // prologue: stages 0,1
    #pragma unroll
    for (int pk = 0; pk < 2; pk++) {
        unsigned st = sbase + (unsigned)((pk % 3) * SSZ * 4);
        #pragma unroll
        for (int i = 0; i < NCH; i++)
            asm volatile("cp.async.cg.shared.global [%0], [%1], 16;" ::
                         "r"(st + dst[i]), "l"(src[i] + (size_t)pk * 16));
        asm volatile("cp.async.commit_group;");
    }

    float acc[MT][NT][4];
    #pragma unroll
    for (int i = 0; i < MT; i++)
        #pragma unroll
        for (int j = 0; j < NT; j++)
            #pragma unroll
            for (int r = 0; r < 4; r++) acc[i][j][r] = 0.f;

    for (int kt = 0; kt < T; kt++) {
        asm volatile("cp.async.wait_group 1;");
        __syncthreads();

        const float* sA = sm + (kt % 3) * SSZ;
        const float* sB = sA + BM * SROW;

        #pragma unroll
        for (int ks = 0; ks < 16; ks += 8) {
            unsigned af[MT][4], bf[NT][2];
            #pragma unroll
            for (int mi = 0; mi < MT; mi++) {
                const float* ar0 = sA + (wm + mi * 16 + grp) * SROW + ks;
                const float* ar1 = ar0 + 8 * SROW;
                af[mi][0] = __float_as_uint(ar0[tg]);
                af[mi][1] = __float_as_uint(ar1[tg]);
                af[mi][2] = __float_as_uint(ar0[tg + 4]);
                af[mi][3] = __float_as_uint(ar1[tg + 4]);
            }
            #pragma unroll
            for (int ni = 0; ni < NT; ni++) {
                const float* br = sB + (wn + ni * 8 + grp) * SROW + ks;
                bf[ni][0] = __float_as_uint(br[tg]);
                bf[ni][1] = __float_as_uint(br[tg + 4]);
            }
            #pragma unroll
            for (int mi = 0; mi < MT; mi++)
                #pragma unroll
                for (int ni = 0; ni < NT; ni++) {
                    asm volatile(
                        "mma.sync.aligned.m16n8k8.row.col.f32.tf32.tf32.f32 "
                        "{%0,%1,%2,%3}, {%4,%5,%6,%7}, {%8,%9}, {%0,%1,%2,%3};"
                        : "+f"(acc[mi][ni][0]), "+f"(acc[mi][ni][1]),
                          "+f"(acc[mi][ni][2]), "+f"(acc[mi][ni][3])
                        : "r"(af[mi][0]), "r"(af[mi][1]), "r"(af[mi][2]), "r"(af[mi][3]),
                          "r"(bf[ni][0]), "r"(bf[ni][1]));
                }
        }

        // issue stage kt+2 (overwrites stage (kt-1)%3, consumed by all warps
        // before the __syncthreads at this iteration's top)
        {
            int nk = kt + 2;
            if (nk < T) {
                unsigned st = sbase + (unsigned)((nk % 3) * SSZ * 4);
                #pragma unroll
                for (int i = 0; i < NCH; i++)
                    asm volatile("cp.async.cg.shared.global [%0], [%1], 16;" ::
                                 "r"(st + dst[i]), "l"(src[i] + (size_t)nk * 16));
            }
            asm volatile("cp.async.commit_group;");
        }
    }

    // epilogue: bias (+ReLU), float2 stores
    #pragma unroll
    for (int mi = 0; mi < MT; mi++) {
        const int row = m0 + wm + mi * 16 + grp;
        #pragma unroll
        for (int ni = 0; ni < NT; ni++) {
            const int lcol = wn + ni * 8 + tg * 2;
            float2 bv = *(const float2*)&buse[lcol];
            float2 o0, o1;
            o0.x = acc[mi][ni][0] + bv.x;
            o0.y = acc[mi][ni][1] + bv.y;
            o1.x = acc[mi][ni][2] + bv.x;
            o1.y = acc[mi][ni][3] + bv.y;
            if (RELU) {
                o0.x = fmaxf(o0.x, 0.f); o0.y = fmaxf(o0.y, 0.f);
                o1.x = fmaxf(o1.x, 0.f); o1.y = fmaxf(o1.y, 0.f);
            }
            *(float2*)&Cout[(size_t)row * ldc + n0 + lcol]       = o0;
            *(float2*)&Cout[(size_t)(row + 8) * ldc + n0 + lcol] = o1;
        }
    }
}

// ---------------- flash-style MHA (reads fused QKV, stride 768) -------------
__global__ __launch_bounds__(128)
void attn_kernel(const float* __restrict__ QKV, float* __restrict__ O) {
    __shared__ float Ks[32][DH];
    __shared__ float Vs[32][DH];
    const int b = blockIdx.z, h = blockIdx.y;
    const int q = blockIdx.x * 128 + threadIdx.x;
    const float scale = 0.17677669529663687f; // 1/sqrt(32)

    const float* qptr = QKV + ((size_t)(b * LQ + q) * 768) + h * DH;
    float qr[DH];
    #pragma unroll
    for (int d = 0; d < DH; d++) qr[d] = qptr[d] * scale;

    float m = -INFINITY, l = 0.f;
    float acc[DH] = {};

    for (int k0 = 0; k0 < LQ; k0 += 32) {
        #pragma unroll
        for (int i = 0; i < 8; i++) {
            int idx = threadIdx.x + i * 128;
            int row = idx >> 5, d = idx & 31;
            size_t base = ((size_t)(b * LQ + k0 + row)) * 768 + h * DH + d;
            Ks[row][d] = QKV[base + 256];
            Vs[row][d] = QKV[base + 512];
        }
        __syncthreads();

        float s[32];
        float tmax = m;
        #pragma unroll
        for (int kk = 0; kk < 32; kk++) {
            float dot = 0.f;
            #pragma unroll
            for (int d = 0; d < DH; d++) dot = fmaf(qr[d], Ks[kk][d], dot);
            s[kk] = dot;
            tmax = fmaxf(tmax, dot);
        }
        float corr = __expf(m - tmax);
        m = tmax;
        float lsum = 0.f;
        #pragma unroll
        for (int kk = 0; kk < 32; kk++) { s[kk] = __expf(s[kk] - m); lsum += s[kk]; }
        l = l * corr + lsum;
        #pragma unroll
        for (int d = 0; d < DH; d++) acc[d] *= corr;
        #pragma unroll
        for (int kk = 0; kk < 32; kk++)
            #pragma unroll
            for (int d = 0; d < DH; d++)
                acc[d] = fmaf(s[kk], Vs[kk][d], acc[d]);
        __syncthreads();
    }
    float inv = 1.f / l;
    float* optr = O + ((size_t)(b * LQ + q) * Cc) + h * DH;
    #pragma unroll
    for (int d = 0; d < DH; d++) optr[d] = acc[d] * inv;
}

// ---------------- LayerNorm( X + R ) ----------------------------------------
__global__ __launch_bounds__(256)
void ln_kernel(const float* __restrict__ X, const float* __restrict__ R,
               const float* __restrict__ g, const float* __restrict__ bta,
               float* __restrict__ O, int nrows) {
    int warp = (blockIdx.x * blockDim.x + threadIdx.x) >> 5;
    int lane = threadIdx.x & 31;
    if (warp >= nrows) return;
    const float* x = X + (size_t)warp * Cc;
    const float* r = R + (size_t)warp * Cc;
    float vals[8];
    float sum = 0.f, sq = 0.f;
    #pragma unroll
    for (int i = 0; i < 8; i++) {
        float v = x[lane + 32 * i] + r[lane + 32 * i];
        vals[i] = v; sum += v; sq = fmaf(v, v, sq);
    }
    #pragma unroll
    for (int o = 16; o; o >>= 1) {
        sum += __shfl_xor_sync(0xffffffffu, sum, o);
        sq  += __shfl_xor_sync(0xffffffffu, sq, o);
    }
    float mean = sum * (1.f / Cc);
    float var  = sq * (1.f / Cc) - mean * mean;
    float inv  = rsqrtf(var + 1e-5f);
    float* out = O + (size_t)warp * Cc;
    #pragma unroll
    for (int i = 0; i < 8; i++) {
        int c = lane + 32 * i;
        out[c] = (vals[i] - mean) * inv * g[c] + bta[c];
    }
}

// ---------------- deformable sampling (reads fused off|aw, stride 384) ------
__device__ __forceinline__ float dsample(const float* __restrict__ vbase,
                                         int ix, int iy, int W, int Hl) {
    if (ix < 0 || ix >= W || iy < 0 || iy >= Hl) return 0.f;
    return vbase[(size_t)(iy * W + ix) * Cc];
}

__global__ __launch_bounds__(256)
void deform_kernel(const float* __restrict__ ref, const float* __restrict__ offaw,
                   const float* __restrict__ val, float* __restrict__ O) {
    int gw = (blockIdx.x * blockDim.x + threadIdx.x) >> 5;
    int lane = threadIdx.x & 31;
    if (gw >= Bz * LQ * Hh) return;
    int h  = gw % Hh;
    int bq = gw / Hh;
    int b  = bq / LQ;

    const float* ap = offaw + (size_t)bq * 384 + 256 + h * (Ll * Pp);
    float w[16];
    float mx = -INFINITY;
    #pragma unroll
    for (int j = 0; j < 16; j++) { w[j] = ap[j]; mx = fmaxf(mx, w[j]); }
    float s = 0.f;
    #pragma unroll
    for (int j = 0; j < 16; j++) { w[j] = __expf(w[j] - mx); s += w[j]; }
    float invs = 1.f / s;

    const float* op = offaw + (size_t)bq * 384 + h * (Ll * Pp * 2);
    const float* rp = ref + (size_t)bq * (Ll * 2);

    float acc = 0.f;
    int start = 0;
    #pragma unroll
    for (int l = 0; l < 4; l++) {
        const int Wl = 128 >> l;
        const int Hl = 128 >> l;
        const float invW = 1.f / Wl, invH = 1.f / Hl;
        float rx = rp[l * 2], ry = rp[l * 2 + 1];
        const float* vbase = val + ((size_t)b * LSRC + start) * Cc + h * DH + lane;
        #pragma unroll
        for (int p = 0; p < 4; p++) {
            float locx = rx + op[l * 8 + p * 2 + 0] * invW;
            float locy = ry + op[l * 8 + p * 2 + 1] * invH;
            float x = locx * Wl - 0.5f;
            float y = locy * Hl - 0.5f;
            float x0f = floorf(x), y0f = floorf(y);
            int   x0 = (int)x0f, y0 = (int)y0f;
            float wx1 = x - x0f, wx0 = 1.f - wx1;
            float wy1 = y - y0f, wy0 = 1.f - wy1;
            float v00 = dsample(vbase, x0,     y0,     Wl, Hl);
            float v10 = dsample(vbase, x0 + 1, y0,     Wl, Hl);
            float v01 = dsample(vbase, x0,     y0 + 1, Wl, Hl);
            float v11 = dsample(vbase, x0 + 1, y0 + 1, Wl, Hl);
            float bil = v00 * wx0 * wy0 + v10 * wx1 * wy0
                      + v01 * wx0 * wy1 + v11 * wx1 * wy1;
            acc = fmaf(w[l * 4 + p] * invs, bil, acc);
        }
        start += Wl * Hl;
    }
    O[(size_t)bq * Cc + h * DH + lane] = acc;
}

// ---------------- host orchestration ----------------------------------------
#define NSPLIT_NONE (1 << 30)

extern "C" void kernel_launch(void* const* d_in, const int* in_sizes, int n_in,
                              void* d_out, int out_size) {
    const float* tgt   = (const float*)d_in[0];
    const float* qpos  = (const float*)d_in[1];
    const float* refp  = (const float*)d_in[2];
    const float* src   = (const float*)d_in[3];
    const float* in_w  = (const float*)d_in[4];
    const float* in_b  = (const float*)d_in[5];
    const float* sa_w  = (const float*)d_in[6];
    const float* sa_b  = (const float*)d_in[7];
    const float* off_w = (const float*)d_in[8];
    const float* off_b = (const float*)d_in[9];
    const float* aw_w  = (const float*)d_in[10];
    const float* aw_b  = (const float*)d_in[11];
    const float* val_w = (const float*)d_in[12];
    const float* val_b = (const float*)d_in[13];
    const float* co_w  = (const float*)d_in[14];
    const float* co_b  = (const float*)d_in[15];
    const float* ln1_g = (const float*)d_in[16];
    const float* ln1_b = (const float*)d_in[17];
    const float* ln2_g = (const float*)d_in[18];
    const float* ln2_b = (const float*)d_in[19];
    const float* ln3_g = (const float*)d_in[20];
    const float* ln3_b = (const float*)d_in[21];
    const float* f1_w  = (const float*)d_in[22];
    const float* f1_b  = (const float*)d_in[23];
    const float* f2_w  = (const float*)d_in[24];
    const float* f2_b  = (const float*)d_in[25];
    float* out = (float*)d_out;

    static float *p_qk=nullptr,*p_qkv,*p_att,*p_sa,*p_tgt1,*p_query,
                 *p_value,*p_offaw,*p_samp,*p_co,*p_tgt2,*p_ffn,*p_f2;
    if (!p_qk) {
        cudaGetSymbolAddress((void**)&p_qk,    g_qk);
        cudaGetSymbolAddress((void**)&p_qkv,   g_qkv);
        cudaGetSymbolAddress((void**)&p_att,   g_att);
        cudaGetSymbolAddress((void**)&p_sa,    g_sa);
        cudaGetSymbolAddress((void**)&p_tgt1,  g_tgt1);
        cudaGetSymbolAddress((void**)&p_query, g_query);
        cudaGetSymbolAddress((void**)&p_value, g_value);
        cudaGetSymbolAddress((void**)&p_offaw, g_offaw);
        cudaGetSymbolAddress((void**)&p_samp,  g_samp);
        cudaGetSymbolAddress((void**)&p_co,    g_co);
        cudaGetSymbolAddress((void**)&p_tgt2,  g_tgt2);
        cudaGetSymbolAddress((void**)&p_ffn,   g_ffn);
        cudaGetSymbolAddress((void**)&p_f2,    g_f2);
    }

    // dynamic smem sizes: 3 stages * (BM+128) rows * 20 floats * 4 B
    const int SMEM_A = 3 * (128 + 128) * SROW * 4;   // 61440 (MT=4)
    const int SMEM_B = 3 * ( 64 + 128) * SROW * 4;   // 46080 (MT=2)
    cudaFuncSetAttribute(gemm_tc<0,4>, cudaFuncAttributeMaxDynamicSharedMemorySize, SMEM_A);
    cudaFuncSetAttribute(gemm_tc<1,4>, cudaFuncAttributeMaxDynamicSharedMemorySize, SMEM_A);
    cudaFuncSetAttribute(gemm_tc<0,2>, cudaFuncAttributeMaxDynamicSharedMemorySize, SMEM_B);

    const int NTOK = Bz * LQ;            // 4096
    const int NELT = NTOK * Cc;          // 1,048,576

    // ---- self-attention branch ----
    add2_kernel<<<(NELT/4 + 255) / 256, 256>>>((const float4*)tgt, (const float4*)qpos,
                                               (float4*)p_qk, NELT / 4);
    // fused QKV: N=768, A = qk for n<512 (Q,K), tgt for n>=512 (V)
    gemm_tc<0,4><<<dim3(768/128, NTOK/128), 256, SMEM_A>>>(
        p_qk, tgt, 512, in_w, in_w, NSPLIT_NONE, in_b, in_b,
        p_qkv, 768, NTOK, 768, Cc);
    attn_kernel<<<dim3(LQ / 128, Hh, Bz), 128>>>(p_qkv, p_att);
    gemm_tc<0,2><<<dim3(Cc/128, NTOK/64), 256, SMEM_B>>>(
        p_att, p_att, NSPLIT_NONE, sa_w, sa_w, NSPLIT_NONE, sa_b, sa_b,
        p_sa, Cc, NTOK, Cc, Cc);
    ln_kernel<<<(NTOK * 32 + 255) / 256, 256>>>(tgt, p_sa, ln2_g, ln2_b, p_tgt1, NTOK);

    // ---- deformable cross-attention branch ----
    add2_kernel<<<(NELT/4 + 255) / 256, 256>>>((const float4*)p_tgt1, (const float4*)qpos,
                                               (float4*)p_query, NELT / 4);
    gemm_tc<0,4><<<dim3(Cc/128, Bz*LSRC/128), 256, SMEM_A>>>(
        src, src, NSPLIT_NONE, val_w, val_w, NSPLIT_NONE, val_b, val_b,
        p_value, Cc, Bz * LSRC, Cc, Cc);
    // fused off|aw: N=384, W = off_w for n<256, aw_w for n>=256
    gemm_tc<0,2><<<dim3(384/128, NTOK/64), 256, SMEM_B>>>(
        p_query, p_query, NSPLIT_NONE, off_w, aw_w, 256, off_b, aw_b,
        p_offaw, 384, NTOK, 384, Cc);
    deform_kernel<<<(Bz * LQ * Hh * 32 + 255) / 256, 256>>>(refp, p_offaw, p_value, p_samp);
    gemm_tc<0,2><<<dim3(Cc/128, NTOK/64), 256, SMEM_B>>>(
        p_samp, p_samp, NSPLIT_NONE, co_w, co_w, NSPLIT_NONE, co_b, co_b,
        p_co, Cc, NTOK, Cc, Cc);
    ln_kernel<<<(NTOK * 32 + 255) / 256, 256>>>(p_tgt1, p_co, ln1_g, ln1_b, p_tgt2, NTOK);

    // ---- FFN ----
    gemm_tc<1,4><<<dim3(DFF/128, NTOK/128), 256, SMEM_A>>>(
        p_tgt2, p_tgt2, NSPLIT_NONE, f1_w, f1_w, NSPLIT_NONE, f1_b, f1_b,
        p_ffn, DFF, NTOK, DFF, Cc);
    gemm_tc<0,2><<<dim3(Cc/128, NTOK/64), 256, SMEM_B>>>(
        p_ffn, p_ffn, NSPLIT_NONE, f2_w, f2_w, NSPLIT_NONE, f2_b, f2_b,
        p_f2, Cc, NTOK, Cc, DFF);
    ln_kernel<<<(NTOK * 32 + 255) / 256, 256>>>(p_tgt2, p_f2, ln3_g, ln3_b, out, NTOK);
}

// round 12
// speedup vs baseline: 1.2781x; 1.2781x over previous
#include <cuda_runtime.h>
#include <math.h>

#define Bz   4
#define LQ   1024
#define Cc   256
#define Hh   8
#define Ll   4
#define Pp   4
#define DFF  1024
#define DH   32
#define LSRC 21760   // 128*128 + 64*64 + 32*32 + 16*16

// ---------------- scratch (static device globals; no allocation) ------------
__device__ float g_qk   [Bz*LQ*Cc];
__device__ float g_q    [Bz*LQ*Cc];
__device__ float g_k    [Bz*LQ*Cc];
__device__ float g_v    [Bz*LQ*Cc];
__device__ float g_att  [Bz*LQ*Cc];
__device__ float g_sa   [Bz*LQ*Cc];
__device__ float g_tgt1 [Bz*LQ*Cc];
__device__ float g_query[Bz*LQ*Cc];
__device__ float g_value[Bz*LSRC*Cc];
__device__ float g_off  [Bz*LQ*Hh*Ll*Pp*2];
__device__ float g_awl  [Bz*LQ*Hh*Ll*Pp];
__device__ float g_samp [Bz*LQ*Cc];
__device__ float g_co   [Bz*LQ*Cc];
__device__ float g_tgt2 [Bz*LQ*Cc];
__device__ float g_ffn  [Bz*LQ*DFF];
__device__ float g_f2   [Bz*LQ*Cc];

// ---------------- elementwise add -------------------------------------------
__global__ void add2_kernel(const float4* __restrict__ a, const float4* __restrict__ b,
                            float4* __restrict__ o, int n4) {
    int i = blockIdx.x * blockDim.x + threadIdx.x;
    if (i < n4) {
        float4 x = a[i], y = b[i];
        x.x += y.x; x.y += y.y; x.z += y.z; x.w += y.w;
        o[i] = x;
    }
}

// ---------------- TF32 tensor-core GEMM: C = A[M,K] @ W[N,K]^T + bias -------
// Block tile 128x128, 256 threads (8 warps, 2x4), warp tile 64x32,
// mma.sync.m16n8k8.tf32, double-buffered smem, k-major layout pad 132.
// Requirements: M%128==0, N%128==0, K%16==0 (true for all calls here).
#define TBM 128
#define TBN 128
#define TBK 16

__device__ __forceinline__ float f2tf32(float x) {
    unsigned r;
    asm("cvt.rna.tf32.f32 %0, %1;" : "=r"(r) : "f"(x));
    return __uint_as_float(r);
}

template<int RELU>
__global__ __launch_bounds__(256)
void gemm_tc(const float* __restrict__ A, const float* __restrict__ W,
             const float* __restrict__ bias, float* __restrict__ Cout,
             int M, int N, int K) {
    __shared__ float As[2][TBK][TBM + 4];   // [k][m], pad 132
    __shared__ float Bs[2][TBK][TBN + 4];   // [k][n], pad 132

    const int n0 = blockIdx.x * TBN;
    const int m0 = blockIdx.y * TBM;
    const int t  = threadIdx.x;
    const int lane = t & 31;
    const int wid  = t >> 5;
    const int wm   = (wid & 1) * 64;   // warp M offset in tile
    const int wn   = (wid >> 1) * 32;  // warp N offset in tile
    const int grp  = lane >> 2;        // 0..7
    const int tg   = lane & 3;         // 0..3

    // global-load mapping: float4 along K, 2 rows each of A and W per thread
    const int lrow = t >> 2;           // 0..63
    const int lc4  = (t & 3) * 4;      // k offset

    const float* Arow0 = A + (size_t)(m0 + lrow)      * K + lc4;
    const float* Arow1 = A + (size_t)(m0 + lrow + 64) * K + lc4;
    const float* Wrow0 = W + (size_t)(n0 + lrow)      * K + lc4;
    const float* Wrow1 = W + (size_t)(n0 + lrow + 64) * K + lc4;

    float acc[4][4][4];
    #pragma unroll
    for (int i = 0; i < 4; i++)
        #pragma unroll
        for (int j = 0; j < 4; j++)
            #pragma unroll
            for (int r = 0; r < 4; r++) acc[i][j][r] = 0.f;

    // ---- prologue: tile 0 -> buffer 0 ----
    {
        float4 a0 = *(const float4*)Arow0;
        float4 a1 = *(const float4*)Arow1;
        float4 b0 = *(const float4*)Wrow0;
        float4 b1 = *(const float4*)Wrow1;
        As[0][lc4+0][lrow]      = f2tf32(a0.x);
        As[0][lc4+1][lrow]      = f2tf32(a0.y);
        As[0][lc4+2][lrow]      = f2tf32(a0.z);
        As[0][lc4+3][lrow]      = f2tf32(a0.w);
        As[0][lc4+0][lrow + 64] = f2tf32(a1.x);
        As[0][lc4+1][lrow + 64] = f2tf32(a1.y);
        As[0][lc4+2][lrow + 64] = f2tf32(a1.z);
        As[0][lc4+3][lrow + 64] = f2tf32(a1.w);
        Bs[0][lc4+0][lrow]      = f2tf32(b0.x);
        Bs[0][lc4+1][lrow]      = f2tf32(b0.y);
        Bs[0][lc4+2][lrow]      = f2tf32(b0.z);
        Bs[0][lc4+3][lrow]      = f2tf32(b0.w);
        Bs[0][lc4+0][lrow + 64] = f2tf32(b1.x);
        Bs[0][lc4+1][lrow + 64] = f2tf32(b1.y);
        Bs[0][lc4+2][lrow + 64] = f2tf32(b1.z);
        Bs[0][lc4+3][lrow + 64] = f2tf32(b1.w);
    }
    __syncthreads();

    int cur = 0;
    for (int k0 = TBK; k0 <= K; k0 += TBK) {
        const bool more = (k0 < K);
        float4 pa0, pa1, pb0, pb1;
        if (more) {
            pa0 = *(const float4*)(Arow0 + k0);
            pa1 = *(const float4*)(Arow1 + k0);
            pb0 = *(const float4*)(Wrow0 + k0);
            pb1 = *(const float4*)(Wrow1 + k0);
        }

        // ---- compute current buffer: 2 k8-steps ----
        #pragma unroll
        for (int ks = 0; ks < TBK; ks += 8) {
            unsigned af[4][4], bf[4][2];
            #pragma unroll
            for (int mi = 0; mi < 4; mi++) {
                af[mi][0] = __float_as_uint(As[cur][ks + tg    ][wm + mi*16 + grp    ]);
                af[mi][1] = __float_as_uint(As[cur][ks + tg    ][wm + mi*16 + grp + 8]);
                af[mi][2] = __float_as_uint(As[cur][ks + tg + 4][wm + mi*16 + grp    ]);
                af[mi][3] = __float_as_uint(As[cur][ks + tg + 4][wm + mi*16 + grp + 8]);
            }
            #pragma unroll
            for (int ni = 0; ni < 4; ni++) {
                bf[ni][0] = __float_as_uint(Bs[cur][ks + tg    ][wn + ni*8 + grp]);
                bf[ni][1] = __float_as_uint(Bs[cur][ks + tg + 4][wn + ni*8 + grp]);
            }
            #pragma unroll
            for (int mi = 0; mi < 4; mi++)
                #pragma unroll
                for (int ni = 0; ni < 4; ni++) {
                    asm volatile(
                        "mma.sync.aligned.m16n8k8.row.col.f32.tf32.tf32.f32 "
                        "{%0,%1,%2,%3}, {%4,%5,%6,%7}, {%8,%9}, {%0,%1,%2,%3};"
                        : "+f"(acc[mi][ni][0]), "+f"(acc[mi][ni][1]),
                          "+f"(acc[mi][ni][2]), "+f"(acc[mi][ni][3])
                        : "r"(af[mi][0]), "r"(af[mi][1]), "r"(af[mi][2]), "r"(af[mi][3]),
                          "r"(bf[ni][0]), "r"(bf[ni][1]));
                }
        }

        if (more) {
            int nxt = cur ^ 1;
            As[nxt][lc4+0][lrow]      = f2tf32(pa0.x);
            As[nxt][lc4+1][lrow]      = f2tf32(pa0.y);
            As[nxt][lc4+2][lrow]      = f2tf32(pa0.z);
            As[nxt][lc4+3][lrow]      = f2tf32(pa0.w);
            As[nxt][lc4+0][lrow + 64] = f2tf32(pa1.x);
            As[nxt][lc4+1][lrow + 64] = f2tf32(pa1.y);
            As[nxt][lc4+2][lrow + 64] = f2tf32(pa1.z);
            As[nxt][lc4+3][lrow + 64] = f2tf32(pa1.w);
            Bs[nxt][lc4+0][lrow]      = f2tf32(pb0.x);
            Bs[nxt][lc4+1][lrow]      = f2tf32(pb0.y);
            Bs[nxt][lc4+2][lrow]      = f2tf32(pb0.z);
            Bs[nxt][lc4+3][lrow]      = f2tf32(pb0.w);
            Bs[nxt][lc4+0][lrow + 64] = f2tf32(pb1.x);
            Bs[nxt][lc4+1][lrow + 64] = f2tf32(pb1.y);
            Bs[nxt][lc4+2][lrow + 64] = f2tf32(pb1.z);
            Bs[nxt][lc4+3][lrow + 64] = f2tf32(pb1.w);
            __syncthreads();
            cur = nxt;
        }
    }

    // ---- epilogue: bias (+ optional ReLU), float2 stores ----
    #pragma unroll
    for (int mi = 0; mi < 4; mi++) {
        const int row = m0 + wm + mi * 16 + grp;
        #pragma unroll
        for (int ni = 0; ni < 4; ni++) {
            const int col = n0 + wn + ni * 8 + tg * 2;
            float2 bv = *(const float2*)&bias[col];
            float2 o0, o1;
            o0.x = acc[mi][ni][0] + bv.x;
            o0.y = acc[mi][ni][1] + bv.y;
            o1.x = acc[mi][ni][2] + bv.x;
            o1.y = acc[mi][ni][3] + bv.y;
            if (RELU) {
                o0.x = fmaxf(o0.x, 0.f); o0.y = fmaxf(o0.y, 0.f);
                o1.x = fmaxf(o1.x, 0.f); o1.y = fmaxf(o1.y, 0.f);
            }
            *(float2*)&Cout[(size_t)row * N + col]       = o0;
            *(float2*)&Cout[(size_t)(row + 8) * N + col] = o1;
        }
    }
}

// ---------------- flash-style MHA -------------------------------------------
__global__ __launch_bounds__(128)
void attn_kernel(const float* __restrict__ Q, const float* __restrict__ Kg,
                 const float* __restrict__ Vg, float* __restrict__ O) {
    __shared__ float Ks[32][DH];
    __shared__ float Vs[32][DH];
    const int b = blockIdx.z, h = blockIdx.y;
    const int q = blockIdx.x * 128 + threadIdx.x;
    const float scale = 0.17677669529663687f; // 1/sqrt(32)

    const float* qptr = Q + ((size_t)(b * LQ + q) * Cc) + h * DH;
    float qr[DH];
    #pragma unroll
    for (int d = 0; d < DH; d++) qr[d] = qptr[d] * scale;

    float m = -INFINITY, l = 0.f;
    float acc[DH] = {};
    const size_t headOff = (size_t)b * LQ * Cc + h * DH;

    for (int k0 = 0; k0 < LQ; k0 += 32) {
        #pragma unroll
        for (int i = 0; i < 8; i++) {
            int idx = threadIdx.x + i * 128;
            int row = idx >> 5, d = idx & 31;
            Ks[row][d] = Kg[headOff + (size_t)(k0 + row) * Cc + d];
            Vs[row][d] = Vg[headOff + (size_t)(k0 + row) * Cc + d];
        }
        __syncthreads();

        float s[32];
        float tmax = m;
        #pragma unroll
        for (int kk = 0; kk < 32; kk++) {
            float dot = 0.f;
            #pragma unroll
            for (int d = 0; d < DH; d++) dot = fmaf(qr[d], Ks[kk][d], dot);
            s[kk] = dot;
            tmax = fmaxf(tmax, dot);
        }
        float corr = __expf(m - tmax);
        m = tmax;
        float lsum = 0.f;
        #pragma unroll
        for (int kk = 0; kk < 32; kk++) { s[kk] = __expf(s[kk] - m); lsum += s[kk]; }
        l = l * corr + lsum;
        #pragma unroll
        for (int d = 0; d < DH; d++) acc[d] *= corr;
        #pragma unroll
        for (int kk = 0; kk < 32; kk++)
            #pragma unroll
            for (int d = 0; d < DH; d++)
                acc[d] = fmaf(s[kk], Vs[kk][d], acc[d]);
        __syncthreads();
    }
    float inv = 1.f / l;
    float* optr = O + ((size_t)(b * LQ + q) * Cc) + h * DH;
    #pragma unroll
    for (int d = 0; d < DH; d++) optr[d] = acc[d] * inv;
}

// ---------------- LayerNorm( X + R ) ----------------------------------------
__global__ __launch_bounds__(256)
void ln_kernel(const float* __restrict__ X, const float* __restrict__ R,
               const float* __restrict__ g, const float* __restrict__ bta,
               float* __restrict__ O, int nrows) {
    int warp = (blockIdx.x * blockDim.x + threadIdx.x) >> 5;
    int lane = threadIdx.x & 31;
    if (warp >= nrows) return;
    const float* x = X + (size_t)warp * Cc;
    const float* r = R + (size_t)warp * Cc;
    float vals[8];
    float sum = 0.f, sq = 0.f;
    #pragma unroll
    for (int i = 0; i < 8; i++) {
        float v = x[lane + 32 * i] + r[lane + 32 * i];
        vals[i] = v; sum += v; sq = fmaf(v, v, sq);
    }
    #pragma unroll
    for (int o = 16; o; o >>= 1) {
        sum += __shfl_xor_sync(0xffffffffu, sum, o);
        sq  += __shfl_xor_sync(0xffffffffu, sq, o);
    }
    float mean = sum * (1.f / Cc);
    float var  = sq * (1.f / Cc) - mean * mean;
    float inv  = rsqrtf(var + 1e-5f);
    float* out = O + (size_t)warp * Cc;
    #pragma unroll
    for (int i = 0; i < 8; i++) {
        int c = lane + 32 * i;
        out[c] = (vals[i] - mean) * inv * g[c] + bta[c];
    }
}

// ---------------- deformable sampling (softmax(aw) fused) --------------------
__device__ __forceinline__ float dsample(const float* __restrict__ vbase,
                                         int ix, int iy, int W, int Hl) {
    if (ix < 0 || ix >= W || iy < 0 || iy >= Hl) return 0.f;
    return vbase[(size_t)(iy * W + ix) * Cc];
}

__global__ __launch_bounds__(256)
void deform_kernel(const float* __restrict__ ref, const float* __restrict__ off,
                   const float* __restrict__ awl, const float* __restrict__ val,
                   float* __restrict__ O) {
    int gw = (blockIdx.x * blockDim.x + threadIdx.x) >> 5;
    int lane = threadIdx.x & 31;
    if (gw >= Bz * LQ * Hh) return;
    int h  = gw % Hh;
    int bq = gw / Hh;
    int b  = bq / LQ;

    const float* ap = awl + (size_t)bq * (Hh * Ll * Pp) + h * (Ll * Pp);
    float w[16];
    float mx = -INFINITY;
    #pragma unroll
    for (int j = 0; j < 16; j++) { w[j] = ap[j]; mx = fmaxf(mx, w[j]); }
    float s = 0.f;
    #pragma unroll
    for (int j = 0; j < 16; j++) { w[j] = __expf(w[j] - mx); s += w[j]; }
    float invs = 1.f / s;

    const float* op = off + (size_t)bq * (Hh * Ll * Pp * 2) + h * (Ll * Pp * 2);
    const float* rp = ref + (size_t)bq * (Ll * 2);

    float acc = 0.f;
    int start = 0;
    #pragma unroll
    for (int l = 0; l < 4; l++) {
        const int Wl = 128 >> l;
        const int Hl = 128 >> l;
        const float invW = 1.f / Wl, invH = 1.f / Hl;
        float rx = rp[l * 2], ry = rp[l * 2 + 1];
        const float* vbase = val + ((size_t)b * LSRC + start) * Cc + h * DH + lane;
        #pragma unroll
        for (int p = 0; p < 4; p++) {
            float locx = rx + op[l * 8 + p * 2 + 0] * invW;
            float locy = ry + op[l * 8 + p * 2 + 1] * invH;
            float x = locx * Wl - 0.5f;
            float y = locy * Hl - 0.5f;
            float x0f = floorf(x), y0f = floorf(y);
            int   x0 = (int)x0f, y0 = (int)y0f;
            float wx1 = x - x0f, wx0 = 1.f - wx1;
            float wy1 = y - y0f, wy0 = 1.f - wy1;
            float v00 = dsample(vbase, x0,     y0,     Wl, Hl);
            float v10 = dsample(vbase, x0 + 1, y0,     Wl, Hl);
            float v01 = dsample(vbase, x0,     y0 + 1, Wl, Hl);
            float v11 = dsample(vbase, x0 + 1, y0 + 1, Wl, Hl);
            float bil = v00 * wx0 * wy0 + v10 * wx1 * wy0
                      + v01 * wx0 * wy1 + v11 * wx1 * wy1;
            acc = fmaf(w[l * 4 + p] * invs, bil, acc);
        }
        start += Wl * Hl;
    }
    O[(size_t)bq * Cc + h * DH + lane] = acc;
}

// ---------------- host orchestration (multi-stream fork/join) ----------------
extern "C" void kernel_launch(void* const* d_in, const int* in_sizes, int n_in,
                              void* d_out, int out_size) {
    const float* tgt   = (const float*)d_in[0];
    const float* qpos  = (const float*)d_in[1];
    const float* refp  = (const float*)d_in[2];
    const float* src   = (const float*)d_in[3];
    const float* in_w  = (const float*)d_in[4];
    const float* in_b  = (const float*)d_in[5];
    const float* sa_w  = (const float*)d_in[6];
    const float* sa_b  = (const float*)d_in[7];
    const float* off_w = (const float*)d_in[8];
    const float* off_b = (const float*)d_in[9];
    const float* aw_w  = (const float*)d_in[10];
    const float* aw_b  = (const float*)d_in[11];
    const float* val_w = (const float*)d_in[12];
    const float* val_b = (const float*)d_in[13];
    const float* co_w  = (const float*)d_in[14];
    const float* co_b  = (const float*)d_in[15];
    const float* ln1_g = (const float*)d_in[16];
    const float* ln1_b = (const float*)d_in[17];
    const float* ln2_g = (const float*)d_in[18];
    const float* ln2_b = (const float*)d_in[19];
    const float* ln3_g = (const float*)d_in[20];
    const float* ln3_b = (const float*)d_in[21];
    const float* f1_w  = (const float*)d_in[22];
    const float* f1_b  = (const float*)d_in[23];
    const float* f2_w  = (const float*)d_in[24];
    const float* f2_b  = (const float*)d_in[25];
    float* out = (float*)d_out;

    static float *p_qk=nullptr,*p_q,*p_k,*p_v,*p_att,*p_sa,*p_tgt1,*p_query,
                 *p_value,*p_off,*p_awl,*p_samp,*p_co,*p_tgt2,*p_ffn,*p_f2;
    static cudaStream_t s1, s2, s3;
    static cudaEvent_t eRoot, eAdd, eV, eK, eVal, eAw, eAddq;
    if (!p_qk) {
        cudaGetSymbolAddress((void**)&p_qk,    g_qk);
        cudaGetSymbolAddress((void**)&p_q,     g_q);
        cudaGetSymbolAddress((void**)&p_k,     g_k);
        cudaGetSymbolAddress((void**)&p_v,     g_v);
        cudaGetSymbolAddress((void**)&p_att,   g_att);
        cudaGetSymbolAddress((void**)&p_sa,    g_sa);
        cudaGetSymbolAddress((void**)&p_tgt1,  g_tgt1);
        cudaGetSymbolAddress((void**)&p_query, g_query);
        cudaGetSymbolAddress((void**)&p_value, g_value);
        cudaGetSymbolAddress((void**)&p_off,   g_off);
        cudaGetSymbolAddress((void**)&p_awl,   g_awl);
        cudaGetSymbolAddress((void**)&p_samp,  g_samp);
        cudaGetSymbolAddress((void**)&p_co,    g_co);
        cudaGetSymbolAddress((void**)&p_tgt2,  g_tgt2);
        cudaGetSymbolAddress((void**)&p_ffn,   g_ffn);
        cudaGetSymbolAddress((void**)&p_f2,    g_f2);
        cudaStreamCreateWithFlags(&s1, cudaStreamNonBlocking);
        cudaStreamCreateWithFlags(&s2, cudaStreamNonBlocking);
        cudaStreamCreateWithFlags(&s3, cudaStreamNonBlocking);
        cudaEventCreateWithFlags(&eRoot, cudaEventDisableTiming);
        cudaEventCreateWithFlags(&eAdd,  cudaEventDisableTiming);
        cudaEventCreateWithFlags(&eV,    cudaEventDisableTiming);
        cudaEventCreateWithFlags(&eK,    cudaEventDisableTiming);
        cudaEventCreateWithFlags(&eVal,  cudaEventDisableTiming);
        cudaEventCreateWithFlags(&eAw,   cudaEventDisableTiming);
        cudaEventCreateWithFlags(&eAddq, cudaEventDisableTiming);
    }

    const int NTOK = Bz * LQ;            // 4096
    const int NELT = NTOK * Cc;          // 1,048,576
    const cudaStream_t m0 = 0;           // capture (main) stream

    // ---- fork root ----
    cudaEventRecord(eRoot, m0);

    // s1: value GEMM (only needs src) — overlaps entire self-attention branch
    cudaStreamWaitEvent(s1, eRoot, 0);
    gemm_tc<0><<<dim3(Cc / TBN, Bz * LSRC / TBM), 256, 0, s1>>>(
        src, val_w, val_b, p_value, Bz * LSRC, Cc, Cc);
    cudaEventRecord(eVal, s1);

    // s2: V GEMM (only needs tgt)
    cudaStreamWaitEvent(s2, eRoot, 0);
    gemm_tc<0><<<dim3(Cc / TBN, NTOK / TBM), 256, 0, s2>>>(
        tgt, in_w + 2 * Cc * Cc, in_b + 2 * Cc, p_v, NTOK, Cc, Cc);
    cudaEventRecord(eV, s2);

    // main: qk = tgt + qpos, then Q GEMM; s3: K GEMM after the add
    add2_kernel<<<(NELT/4 + 255) / 256, 256, 0, m0>>>(
        (const float4*)tgt, (const float4*)qpos, (float4*)p_qk, NELT / 4);
    cudaEventRecord(eAdd, m0);
    cudaStreamWaitEvent(s3, eAdd, 0);
    gemm_tc<0><<<dim3(Cc / TBN, NTOK / TBM), 256, 0, s3>>>(
        p_qk, in_w + Cc * Cc, in_b + Cc, p_k, NTOK, Cc, Cc);
    cudaEventRecord(eK, s3);
    gemm_tc<0><<<dim3(Cc / TBN, NTOK / TBM), 256, 0, m0>>>(
        p_qk, in_w, in_b, p_q, NTOK, Cc, Cc);

    // join V and K, then attention
    cudaStreamWaitEvent(m0, eV, 0);
    cudaStreamWaitEvent(m0, eK, 0);
    attn_kernel<<<dim3(LQ / 128, Hh, Bz), 128, 0, m0>>>(p_q, p_k, p_v, p_att);
    gemm_tc<0><<<dim3(Cc / TBN, NTOK / TBM), 256, 0, m0>>>(
        p_att, sa_w, sa_b, p_sa, NTOK, Cc, Cc);
    ln_kernel<<<(NTOK * 32 + 255) / 256, 256, 0, m0>>>(
        tgt, p_sa, ln2_g, ln2_b, p_tgt1, NTOK);

    // ---- deformable cross-attention branch ----
    add2_kernel<<<(NELT/4 + 255) / 256, 256, 0, m0>>>(
        (const float4*)p_tgt1, (const float4*)qpos, (float4*)p_query, NELT / 4);
    cudaEventRecord(eAddq, m0);
    // s2: aw GEMM concurrent with off GEMM on main
    cudaStreamWaitEvent(s2, eAddq, 0);
    gemm_tc<0><<<dim3(128 / TBN, NTOK / TBM), 256, 0, s2>>>(
        p_query, aw_w, aw_b, p_awl, NTOK, 128, Cc);
    cudaEventRecord(eAw, s2);
    gemm_tc<0><<<dim3(256 / TBN, NTOK / TBM), 256, 0, m0>>>(
        p_query, off_w, off_b, p_off, NTOK, 256, Cc);

    // join aw + value, then sample
    cudaStreamWaitEvent(m0, eAw, 0);
    cudaStreamWaitEvent(m0, eVal, 0);
    deform_kernel<<<(Bz * LQ * Hh * 32 + 255) / 256, 256, 0, m0>>>(
        refp, p_off, p_awl, p_value, p_samp);
    gemm_tc<0><<<dim3(Cc / TBN, NTOK / TBM), 256, 0, m0>>>(
        p_samp, co_w, co_b, p_co, NTOK, Cc, Cc);
    ln_kernel<<<(NTOK * 32 + 255) / 256, 256, 0, m0>>>(
        p_tgt1, p_co, ln1_g, ln1_b, p_tgt2, NTOK);

    // ---- FFN ----
    gemm_tc<1><<<dim3(DFF / TBN, NTOK / TBM), 256, 0, m0>>>(
        p_tgt2, f1_w, f1_b, p_ffn, NTOK, DFF, Cc);
    gemm_tc<0><<<dim3(Cc / TBN, NTOK / TBM), 256, 0, m0>>>(
        p_ffn, f2_w, f2_b, p_f2, NTOK, Cc, DFF);
    ln_kernel<<<(NTOK * 32 + 255) / 256, 256, 0, m0>>>(
        p_tgt2, p_f2, ln3_g, ln3_b, out, NTOK);
}

// round 14
// speedup vs baseline: 1.5268x; 1.1946x over previous
#include <cuda_runtime.h>
#include <math.h>

#define Bz   4
#define LQ   1024
#define Cc   256
#define Hh   8
#define Ll   4
#define Pp   4
#define DFF  1024
#define DH   32
#define LSRC 21760   // 128*128 + 64*64 + 32*32 + 16*16

// ---------------- scratch (static device globals; no allocation) ------------
__device__ float g_qk   [Bz*LQ*Cc];
__device__ float g_q    [Bz*LQ*Cc];
__device__ float g_k    [Bz*LQ*Cc];
__device__ float g_v    [Bz*LQ*Cc];
__device__ float g_att  [Bz*LQ*Cc];
__device__ float g_sa   [Bz*LQ*Cc];
__device__ float g_tgt1 [Bz*LQ*Cc];
__device__ float g_query[Bz*LQ*Cc];
__device__ float g_value[Bz*LSRC*Cc];
__device__ float g_off  [Bz*LQ*Hh*Ll*Pp*2];
__device__ float g_awl  [Bz*LQ*Hh*Ll*Pp];
__device__ float g_samp [Bz*LQ*Cc];
__device__ float g_co   [Bz*LQ*Cc];
__device__ float g_tgt2 [Bz*LQ*Cc];
__device__ float g_ffn  [Bz*LQ*DFF];
__device__ float g_f2   [Bz*LQ*Cc];

// ---------------- elementwise add -------------------------------------------
__global__ void add2_kernel(const float4* __restrict__ a, const float4* __restrict__ b,
                            float4* __restrict__ o, int n4) {
    int i = blockIdx.x * blockDim.x + threadIdx.x;
    if (i < n4) {
        float4 x = a[i], y = b[i];
        x.x += y.x; x.y += y.y; x.z += y.z; x.w += y.w;
        o[i] = x;
    }
}

// ---------------- TF32 tensor-core GEMM, cp.async 3-stage pipeline ----------
// C[M,N] = A[M,K] @ W[N,K]^T + bias.
// Block tile (MT*32) x 128, 256 threads, 8 warps (2 M x 4 N),
// warp tile (MT*16) x 32, mma.m16n8k8.tf32 (raw f32 operands, HW-truncated).
// smem [row][k]: rows 0..BM-1 = A(m), BM..BM+127 = W(n), row stride 20 floats
// (bank-exact conflict-free for both fragment loads and cp.async stores).
// Requirements: M % (MT*32) == 0, N % 128 == 0, K % 16 == 0.
#define SROW 20

template<int RELU, int MT>
__global__ __launch_bounds__(256)
void gemm_tc(const float* __restrict__ A, const float* __restrict__ W,
             const float* __restrict__ bias, float* __restrict__ Cout,
             int M, int N, int K) {
    constexpr int BM   = MT * 32;
    constexpr int BN   = 128;
    constexpr int NT   = 4;
    constexpr int ROWS = BM + BN;
    constexpr int SSZ  = ROWS * SROW;          // floats per stage
    constexpr int NCH  = ROWS * 4 / 256;       // 16B chunks per thread

    extern __shared__ float sm[];

    const int n0 = blockIdx.x * BN;
    const int m0 = blockIdx.y * BM;
    const int t  = threadIdx.x;
    const int lane = t & 31;
    const int wid  = t >> 5;
    const int wm   = (wid & 1) * MT * 16;
    const int wn   = (wid >> 1) * NT * 8;
    const int grp  = lane >> 2;
    const int tg   = lane & 3;

    // per-thread cp.async chunk sources / smem destinations
    const float* src[NCH];
    unsigned dst[NCH];
    #pragma unroll
    for (int i = 0; i < NCH; i++) {
        int chunk = t + i * 256;
        int row = chunk >> 2;
        int off = (chunk & 3) * 4;
        if (row < BM) src[i] = A + (size_t)(m0 + row) * K + off;
        else          src[i] = W + (size_t)(n0 + row - BM) * K + off;
        dst[i] = (unsigned)((row * SROW + off) * 4);
    }
    const unsigned sbase = (unsigned)__cvta_generic_to_shared(sm);
    const int T = K / 16;

    // prologue: stages 0,1
    #pragma unroll
    for (int pk = 0; pk < 2; pk++) {
        unsigned st = sbase + (unsigned)(pk * SSZ * 4);
        #pragma unroll
        for (int i = 0; i < NCH; i++)
            asm volatile("cp.async.cg.shared.global [%0], [%1], 16;" ::
                         "r"(st + dst[i]), "l"(src[i] + (size_t)pk * 16));
        asm volatile("cp.async.commit_group;");
    }

    float acc[MT][NT][4];
    #pragma unroll
    for (int i = 0; i < MT; i++)
        #pragma unroll
        for (int j = 0; j < NT; j++)
            #pragma unroll
            for (int r = 0; r < 4; r++) acc[i][j][r] = 0.f;

    for (int kt = 0; kt < T; kt++) {
        asm volatile("cp.async.wait_group 1;");
        __syncthreads();

        const float* sA = sm + (kt % 3) * SSZ;
        const float* sB = sA + BM * SROW;

        #pragma unroll
        for (int ks = 0; ks < 16; ks += 8) {
            unsigned af[MT][4], bf[NT][2];
            #pragma unroll
            for (int mi = 0; mi < MT; mi++) {
                const float* ar0 = sA + (wm + mi * 16 + grp) * SROW + ks;
                const float* ar1 = ar0 + 8 * SROW;
                af[mi][0] = __float_as_uint(ar0[tg]);
                af[mi][1] = __float_as_uint(ar1[tg]);
                af[mi][2] = __float_as_uint(ar0[tg + 4]);
                af[mi][3] = __float_as_uint(ar1[tg + 4]);
            }
            #pragma unroll
            for (int ni = 0; ni < NT; ni++) {
                const float* br = sB + (wn + ni * 8 + grp) * SROW + ks;
                bf[ni][0] = __float_as_uint(br[tg]);
                bf[ni][1] = __float_as_uint(br[tg + 4]);
            }
            #pragma unroll
            for (int mi = 0; mi < MT; mi++)
                #pragma unroll
                for (int ni = 0; ni < NT; ni++) {
                    asm volatile(
                        "mma.sync.aligned.m16n8k8.row.col.f32.tf32.tf32.f32 "
                        "{%0,%1,%2,%3}, {%4,%5,%6,%7}, {%8,%9}, {%0,%1,%2,%3};"
                        : "+f"(acc[mi][ni][0]), "+f"(acc[mi][ni][1]),
                          "+f"(acc[mi][ni][2]), "+f"(acc[mi][ni][3])
                        : "r"(af[mi][0]), "r"(af[mi][1]), "r"(af[mi][2]), "r"(af[mi][3]),
                          "r"(bf[ni][0]), "r"(bf[ni][1]));
                }
        }

        // issue stage kt+2 (its buffer was consumed before this iter's sync)
        {
            int nk = kt + 2;
            if (nk < T) {
                unsigned st = sbase + (unsigned)((nk % 3) * SSZ * 4);
                #pragma unroll
                for (int i = 0; i < NCH; i++)
                    asm volatile("cp.async.cg.shared.global [%0], [%1], 16;" ::
                                 "r"(st + dst[i]), "l"(src[i] + (size_t)nk * 16));
            }
            asm volatile("cp.async.commit_group;");
        }
    }

    // ---- epilogue: bias (+ optional ReLU), float2 stores ----
    #pragma unroll
    for (int mi = 0; mi < MT; mi++) {
        const int row = m0 + wm + mi * 16 + grp;
        #pragma unroll
        for (int ni = 0; ni < NT; ni++) {
            const int col = n0 + wn + ni * 8 + tg * 2;
            float2 bv = *(const float2*)&bias[col];
            float2 o0, o1;
            o0.x = acc[mi][ni][0] + bv.x;
            o0.y = acc[mi][ni][1] + bv.y;
            o1.x = acc[mi][ni][2] + bv.x;
            o1.y = acc[mi][ni][3] + bv.y;
            if (RELU) {
                o0.x = fmaxf(o0.x, 0.f); o0.y = fmaxf(o0.y, 0.f);
                o1.x = fmaxf(o1.x, 0.f); o1.y = fmaxf(o1.y, 0.f);
            }
            *(float2*)&Cout[(size_t)row * N + col]       = o0;
            *(float2*)&Cout[(size_t)(row + 8) * N + col] = o1;
        }
    }
}

#define SMEM_MT4 (3 * (128 + 128) * SROW * 4)   // 61440
#define SMEM_MT2 (3 * ( 64 + 128) * SROW * 4)   // 46080

// ---------------- flash-style MHA -------------------------------------------
__global__ __launch_bounds__(128)
void attn_kernel(const float* __restrict__ Q, const float* __restrict__ Kg,
                 const float* __restrict__ Vg, float* __restrict__ O) {
    __shared__ float Ks[32][DH];
    __shared__ float Vs[32][DH];
    const int b = blockIdx.z, h = blockIdx.y;
    const int q = blockIdx.x * 128 + threadIdx.x;
    const float scale = 0.17677669529663687f; // 1/sqrt(32)

    const float* qptr = Q + ((size_t)(b * LQ + q) * Cc) + h * DH;
    float qr[DH];
    #pragma unroll
    for (int d = 0; d < DH; d++) qr[d] = qptr[d] * scale;

    float m = -INFINITY, l = 0.f;
    float acc[DH] = {};
    const size_t headOff = (size_t)b * LQ * Cc + h * DH;

    for (int k0 = 0; k0 < LQ; k0 += 32) {
        #pragma unroll
        for (int i = 0; i < 8; i++) {
            int idx = threadIdx.x + i * 128;
            int row = idx >> 5, d = idx & 31;
            Ks[row][d] = Kg[headOff + (size_t)(k0 + row) * Cc + d];
            Vs[row][d] = Vg[headOff + (size_t)(k0 + row) * Cc + d];
        }
        __syncthreads();

        float s[32];
        float tmax = m;
        #pragma unroll
        for (int kk = 0; kk < 32; kk++) {
            float dot = 0.f;
            #pragma unroll
            for (int d = 0; d < DH; d++) dot = fmaf(qr[d], Ks[kk][d], dot);
            s[kk] = dot;
            tmax = fmaxf(tmax, dot);
        }
        float corr = __expf(m - tmax);
        m = tmax;
        float lsum = 0.f;
        #pragma unroll
        for (int kk = 0; kk < 32; kk++) { s[kk] = __expf(s[kk] - m); lsum += s[kk]; }
        l = l * corr + lsum;
        #pragma unroll
        for (int d = 0; d < DH; d++) acc[d] *= corr;
        #pragma unroll
        for (int kk = 0; kk < 32; kk++)
            #pragma unroll
            for (int d = 0; d < DH; d++)
                acc[d] = fmaf(s[kk], Vs[kk][d], acc[d]);
        __syncthreads();
    }
    float inv = 1.f / l;
    float* optr = O + ((size_t)(b * LQ + q) * Cc) + h * DH;
    #pragma unroll
    for (int d = 0; d < DH; d++) optr[d] = acc[d] * inv;
}

// ---------------- LayerNorm( X + R ) ----------------------------------------
__global__ __launch_bounds__(256)
void ln_kernel(const float* __restrict__ X, const float* __restrict__ R,
               const float* __restrict__ g, const float* __restrict__ bta,
               float* __restrict__ O, int nrows) {
    int warp = (blockIdx.x * blockDim.x + threadIdx.x) >> 5;
    int lane = threadIdx.x & 31;
    if (warp >= nrows) return;
    const float* x = X + (size_t)warp * Cc;
    const float* r = R + (size_t)warp * Cc;
    float vals[8];
    float sum = 0.f, sq = 0.f;
    #pragma unroll
    for (int i = 0; i < 8; i++) {
        float v = x[lane + 32 * i] + r[lane + 32 * i];
        vals[i] = v; sum += v; sq = fmaf(v, v, sq);
    }
    #pragma unroll
    for (int o = 16; o; o >>= 1) {
        sum += __shfl_xor_sync(0xffffffffu, sum, o);
        sq  += __shfl_xor_sync(0xffffffffu, sq, o);
    }
    float mean = sum * (1.f / Cc);
    float var  = sq * (1.f / Cc) - mean * mean;
    float inv  = rsqrtf(var + 1e-5f);
    float* out = O + (size_t)warp * Cc;
    #pragma unroll
    for (int i = 0; i < 8; i++) {
        int c = lane + 32 * i;
        out[c] = (vals[i] - mean) * inv * g[c] + bta[c];
    }
}

// ---------------- deformable sampling (softmax(aw) fused) --------------------
__device__ __forceinline__ float dsample(const float* __restrict__ vbase,
                                         int ix, int iy, int W, int Hl) {
    if (ix < 0 || ix >= W || iy < 0 || iy >= Hl) return 0.f;
    return vbase[(size_t)(iy * W + ix) * Cc];
}

__global__ __launch_bounds__(256)
void deform_kernel(const float* __restrict__ ref, const float* __restrict__ off,
                   const float* __restrict__ awl, const float* __restrict__ val,
                   float* __restrict__ O) {
    int gw = (blockIdx.x * blockDim.x + threadIdx.x) >> 5;
    int lane = threadIdx.x & 31;
    if (gw >= Bz * LQ * Hh) return;
    int h  = gw % Hh;
    int bq = gw / Hh;
    int b  = bq / LQ;

    const float* ap = awl + (size_t)bq * (Hh * Ll * Pp) + h * (Ll * Pp);
    float w[16];
    float mx = -INFINITY;
    #pragma unroll
    for (int j = 0; j < 16; j++) { w[j] = ap[j]; mx = fmaxf(mx, w[j]); }
    float s = 0.f;
    #pragma unroll
    for (int j = 0; j < 16; j++) { w[j] = __expf(w[j] - mx); s += w[j]; }
    float invs = 1.f / s;

    const float* op = off + (size_t)bq * (Hh * Ll * Pp * 2) + h * (Ll * Pp * 2);
    const float* rp = ref + (size_t)bq * (Ll * 2);

    float acc = 0.f;
    int start = 0;
    #pragma unroll
    for (int l = 0; l < 4; l++) {
        const int Wl = 128 >> l;
        const int Hl = 128 >> l;
        const float invW = 1.f / Wl, invH = 1.f / Hl;
        float rx = rp[l * 2], ry = rp[l * 2 + 1];
        const float* vbase = val + ((size_t)b * LSRC + start) * Cc + h * DH + lane;
        #pragma unroll
        for (int p = 0; p < 4; p++) {
            float locx = rx + op[l * 8 + p * 2 + 0] * invW;
            float locy = ry + op[l * 8 + p * 2 + 1] * invH;
            float x = locx * Wl - 0.5f;
            float y = locy * Hl - 0.5f;
            float x0f = floorf(x), y0f = floorf(y);
            int   x0 = (int)x0f, y0 = (int)y0f;
            float wx1 = x - x0f, wx0 = 1.f - wx1;
            float wy1 = y - y0f, wy0 = 1.f - wy1;
            float v00 = dsample(vbase, x0,     y0,     Wl, Hl);
            float v10 = dsample(vbase, x0 + 1, y0,     Wl, Hl);
            float v01 = dsample(vbase, x0,     y0 + 1, Wl, Hl);
            float v11 = dsample(vbase, x0 + 1, y0 + 1, Wl, Hl);
            float bil = v00 * wx0 * wy0 + v10 * wx1 * wy0
                      + v01 * wx0 * wy1 + v11 * wx1 * wy1;
            acc = fmaf(w[l * 4 + p] * invs, bil, acc);
        }
        start += Wl * Hl;
    }
    O[(size_t)bq * Cc + h * DH + lane] = acc;
}

// ---------------- host orchestration (multi-stream fork/join) ----------------
extern "C" void kernel_launch(void* const* d_in, const int* in_sizes, int n_in,
                              void* d_out, int out_size) {
    const float* tgt   = (const float*)d_in[0];
    const float* qpos  = (const float*)d_in[1];
    const float* refp  = (const float*)d_in[2];
    const float* src   = (const float*)d_in[3];
    const float* in_w  = (const float*)d_in[4];
    const float* in_b  = (const float*)d_in[5];
    const float* sa_w  = (const float*)d_in[6];
    const float* sa_b  = (const float*)d_in[7];
    const float* off_w = (const float*)d_in[8];
    const float* off_b = (const float*)d_in[9];
    const float* aw_w  = (const float*)d_in[10];
    const float* aw_b  = (const float*)d_in[11];
    const float* val_w = (const float*)d_in[12];
    const float* val_b = (const float*)d_in[13];
    const float* co_w  = (const float*)d_in[14];
    const float* co_b  = (const float*)d_in[15];
    const float* ln1_g = (const float*)d_in[16];
    const float* ln1_b = (const float*)d_in[17];
    const float* ln2_g = (const float*)d_in[18];
    const float* ln2_b = (const float*)d_in[19];
    const float* ln3_g = (const float*)d_in[20];
    const float* ln3_b = (const float*)d_in[21];
    const float* f1_w  = (const float*)d_in[22];
    const float* f1_b  = (const float*)d_in[23];
    const float* f2_w  = (const float*)d_in[24];
    const float* f2_b  = (const float*)d_in[25];
    float* out = (float*)d_out;

    static float *p_qk=nullptr,*p_q,*p_k,*p_v,*p_att,*p_sa,*p_tgt1,*p_query,
                 *p_value,*p_off,*p_awl,*p_samp,*p_co,*p_tgt2,*p_ffn,*p_f2;
    static cudaStream_t s1, s2, s3;
    static cudaEvent_t eRoot, eAdd, eV, eK, eVal, eAw, eAddq;
    if (!p_qk) {
        cudaGetSymbolAddress((void**)&p_qk,    g_qk);
        cudaGetSymbolAddress((void**)&p_q,     g_q);
        cudaGetSymbolAddress((void**)&p_k,     g_k);
        cudaGetSymbolAddress((void**)&p_v,     g_v);
        cudaGetSymbolAddress((void**)&p_att,   g_att);
        cudaGetSymbolAddress((void**)&p_sa,    g_sa);
        cudaGetSymbolAddress((void**)&p_tgt1,  g_tgt1);
        cudaGetSymbolAddress((void**)&p_query, g_query);
        cudaGetSymbolAddress((void**)&p_value, g_value);
        cudaGetSymbolAddress((void**)&p_off,   g_off);
        cudaGetSymbolAddress((void**)&p_awl,   g_awl);
        cudaGetSymbolAddress((void**)&p_samp,  g_samp);
        cudaGetSymbolAddress((void**)&p_co,    g_co);
        cudaGetSymbolAddress((void**)&p_tgt2,  g_tgt2);
        cudaGetSymbolAddress((void**)&p_ffn,   g_ffn);
        cudaGetSymbolAddress((void**)&p_f2,    g_f2);
        cudaStreamCreateWithFlags(&s1, cudaStreamNonBlocking);
        cudaStreamCreateWithFlags(&s2, cudaStreamNonBlocking);
        cudaStreamCreateWithFlags(&s3, cudaStreamNonBlocking);
        cudaEventCreateWithFlags(&eRoot, cudaEventDisableTiming);
        cudaEventCreateWithFlags(&eAdd,  cudaEventDisableTiming);
        cudaEventCreateWithFlags(&eV,    cudaEventDisableTiming);
        cudaEventCreateWithFlags(&eK,    cudaEventDisableTiming);
        cudaEventCreateWithFlags(&eVal,  cudaEventDisableTiming);
        cudaEventCreateWithFlags(&eAw,   cudaEventDisableTiming);
        cudaEventCreateWithFlags(&eAddq, cudaEventDisableTiming);
        cudaFuncSetAttribute(gemm_tc<0,4>, cudaFuncAttributeMaxDynamicSharedMemorySize, SMEM_MT4);
        cudaFuncSetAttribute(gemm_tc<1,4>, cudaFuncAttributeMaxDynamicSharedMemorySize, SMEM_MT4);
        cudaFuncSetAttribute(gemm_tc<0,2>, cudaFuncAttributeMaxDynamicSharedMemorySize, SMEM_MT2);
    }

    const int NTOK = Bz * LQ;            // 4096
    const int NELT = NTOK * Cc;          // 1,048,576
    const cudaStream_t m0 = 0;           // capture (main) stream

    // ---- fork root ----
    cudaEventRecord(eRoot, m0);

    // s1: value GEMM (only needs src) — overlaps entire self-attention branch
    cudaStreamWaitEvent(s1, eRoot, 0);
    gemm_tc<0,4><<<dim3(Cc/128, Bz*LSRC/128), 256, SMEM_MT4, s1>>>(
        src, val_w, val_b, p_value, Bz * LSRC, Cc, Cc);
    cudaEventRecord(eVal, s1);

    // s2: V GEMM (only needs tgt)
    cudaStreamWaitEvent(s2, eRoot, 0);
    gemm_tc<0,2><<<dim3(Cc/128, NTOK/64), 256, SMEM_MT2, s2>>>(
        tgt, in_w + 2 * Cc * Cc, in_b + 2 * Cc, p_v, NTOK, Cc, Cc);
    cudaEventRecord(eV, s2);

    // main: qk = tgt + qpos, then Q GEMM; s3: K GEMM after the add
    add2_kernel<<<(NELT/4 + 255) / 256, 256, 0, m0>>>(
        (const float4*)tgt, (const float4*)qpos, (float4*)p_qk, NELT / 4);
    cudaEventRecord(eAdd, m0);
    cudaStreamWaitEvent(s3, eAdd, 0);
    gemm_tc<0,2><<<dim3(Cc/128, NTOK/64), 256, SMEM_MT2, s3>>>(
        p_qk, in_w + Cc * Cc, in_b + Cc, p_k, NTOK, Cc, Cc);
    cudaEventRecord(eK, s3);
    gemm_tc<0,2><<<dim3(Cc/128, NTOK/64), 256, SMEM_MT2, m0>>>(
        p_qk, in_w, in_b, p_q, NTOK, Cc, Cc);

    // join V and K, then attention
    cudaStreamWaitEvent(m0, eV, 0);
    cudaStreamWaitEvent(m0, eK, 0);
    attn_kernel<<<dim3(LQ / 128, Hh, Bz), 128, 0, m0>>>(p_q, p_k, p_v, p_att);
    gemm_tc<0,2><<<dim3(Cc/128, NTOK/64), 256, SMEM_MT2, m0>>>(
        p_att, sa_w, sa_b, p_sa, NTOK, Cc, Cc);
    ln_kernel<<<(NTOK * 32 + 255) / 256, 256, 0, m0>>>(
        tgt, p_sa, ln2_g, ln2_b, p_tgt1, NTOK);

    // ---- deformable cross-attention branch ----
    add2_kernel<<<(NELT/4 + 255) / 256, 256, 0, m0>>>(
        (const float4*)p_tgt1, (const float4*)qpos, (float4*)p_query, NELT / 4);
    cudaEventRecord(eAddq, m0);
    // s2: aw GEMM concurrent with off GEMM on main
    cudaStreamWaitEvent(s2, eAddq, 0);
    gemm_tc<0,2><<<dim3(128/128, NTOK/64), 256, SMEM_MT2, s2>>>(
        p_query, aw_w, aw_b, p_awl, NTOK, 128, Cc);
    cudaEventRecord(eAw, s2);
    gemm_tc<0,2><<<dim3(256/128, NTOK/64), 256, SMEM_MT2, m0>>>(
        p_query, off_w, off_b, p_off, NTOK, 256, Cc);

    // join aw + value, then sample
    cudaStreamWaitEvent(m0, eAw, 0);
    cudaStreamWaitEvent(m0, eVal, 0);
    deform_kernel<<<(Bz * LQ * Hh * 32 + 255) / 256, 256, 0, m0>>>(
        refp, p_off, p_awl, p_value, p_samp);
    gemm_tc<0,2><<<dim3(Cc/128, NTOK/64), 256, SMEM_MT2, m0>>>(
        p_samp, co_w, co_b, p_co, NTOK, Cc, Cc);
    ln_kernel<<<(NTOK * 32 + 255) / 256, 256, 0, m0>>>(
        p_tgt1, p_co, ln1_g, ln1_b, p_tgt2, NTOK);

    // ---- FFN ----
    gemm_tc<1,4><<<dim3(DFF/128, NTOK/128), 256, SMEM_MT4, m0>>>(
        p_tgt2, f1_w, f1_b, p_ffn, NTOK, DFF, Cc);
    gemm_tc<0,2><<<dim3(Cc/128, NTOK/64), 256, SMEM_MT2, m0>>>(
        p_ffn, f2_w, f2_b, p_f2, NTOK, Cc, DFF);
    ln_kernel<<<(NTOK * 32 + 255) / 256, 256, 0, m0>>>(
        p_tgt2, p_f2, ln3_g, ln3_b, out, NTOK);
}